// round 2
// baseline (speedup 1.0000x reference)
#include <cuda_runtime.h>
#include <stdint.h>

// Problem constants
#define N_SRC0 200000
#define N_DST0 50000
#define N_DST1 10000
#define NE0    800000
#define NE1    160000
#define DIM    256
#define NBASE  4
#define BD     64      // per-block dim of block-diagonal transform
#define NPAIR  5000

// ---------------------------------------------------------------------------
// Scratch (no allocations allowed -> __device__ globals, referenced directly
// from kernels so kernel_launch is pure kernel launches)
// ---------------------------------------------------------------------------
__device__ float g_agg0[(size_t)N_DST0 * DIM];
__device__ float g_agg1[(size_t)N_DST1 * DIM];
__device__ float g_h0  [(size_t)N_DST0 * DIM];
__device__ float g_h1  [(size_t)N_DST1 * DIM];

// ---------------------------------------------------------------------------
// Zero the aggregation buffers (must run before the scatters each call)
// ---------------------------------------------------------------------------
__global__ void zero_kernel() {
    int stride = gridDim.x * blockDim.x;
    int i0 = blockIdx.x * blockDim.x + threadIdx.x;
    float4 z = make_float4(0.f, 0.f, 0.f, 0.f);
    const int tot0 = N_DST0 * DIM / 4;
    float4* a0 = (float4*)g_agg0;
    for (int i = i0; i < tot0; i += stride) a0[i] = z;
    const int tot1 = N_DST1 * DIM / 4;
    float4* a1 = (float4*)g_agg1;
    for (int i = i0; i < tot1; i += stride) a1[i] = z;
}

// ---------------------------------------------------------------------------
// Edge scatter: agg[dst[e], :] += feat[src[e], :]
// 64 threads per edge, float4 loads, scalar atomic adds (RED, no return).
// ---------------------------------------------------------------------------
template <int WHICH>   // 0: feat = input x (param), agg = g_agg0 ; 1: feat = g_h0, agg = g_agg1
__global__ __launch_bounds__(256) void scatter_kernel(
    const float* __restrict__ featp,
    const int*   __restrict__ src,
    const int*   __restrict__ dst,
    int nedges)
{
    const float* feat = (WHICH == 0) ? featp : g_h0;
    float*       agg  = (WHICH == 0) ? g_agg0 : g_agg1;

    int lane = threadIdx.x & 63;              // 0..63, 4 floats each
    int e    = blockIdx.x * 4 + (threadIdx.x >> 6);
    if (e >= nedges) return;
    int s = src[e];
    int d = dst[e];
    float4 v = ((const float4*)feat)[(size_t)s * (DIM / 4) + lane];
    float* a = agg + (size_t)d * DIM + lane * 4;
    atomicAdd(a + 0, v.x);
    atomicAdd(a + 1, v.y);
    atomicAdd(a + 2, v.z);
    atomicAdd(a + 3, v.w);
}

// ---------------------------------------------------------------------------
// Fused layer GEMM:
//   out[r, c] = relu( sum_k xd[r,k] * loopw[k,c]                (dense, K=256)
//                   + sum_k agg[r, cb*64+k] * W[cb,k,c%64]      (bdd,   K=64)
//                   + bias[c] )
// Tile: 64 rows x 64 cols per block, 256 threads, 4x4 register microtile.
// grid = (ceil(M/64), 4 column-blocks)
// LAYER 0: agg=g_agg0, xd=x(param), out=g_h0
// LAYER 1: agg=g_agg1, xd=g_h0,     out=g_h1 (+mirror to d_out)
// ---------------------------------------------------------------------------
template <int LAYER>
__global__ __launch_bounds__(256) void layer_kernel(
    const float* __restrict__ xparam, // layer0: x pointer; layer1: unused
    const float* __restrict__ W,      // [4, 64, 64] block-diagonal weights
    const float* __restrict__ loopw,  // [256, 256] self-loop weight
    const float* __restrict__ bias,   // [256]
    float*       __restrict__ out2,   // optional mirror (may be null)
    int M)
{
    const float* agg = (LAYER == 0) ? g_agg0 : g_agg1;
    const float* xd  = (LAYER == 0) ? xparam : g_h0;
    float*       out = (LAYER == 0) ? g_h0   : g_h1;

    __shared__ float As[64][65];
    __shared__ float Bs[64][64];

    const int cb = blockIdx.y;        // column block 0..3
    const int r0 = blockIdx.x * 64;
    const int tid = threadIdx.x;
    const int tx = tid & 15;          // 0..15 -> 4 cols each
    const int ty = tid >> 4;          // 0..15 -> 4 rows each

    float acc[4][4] = {};

    // Chunks 0..3: dense self-loop GEMM (K = 256). Chunk 4: bdd (K = 64).
    #pragma unroll
    for (int ch = 0; ch < 5; ++ch) {
        const float* srcmat = (ch < 4) ? xd : agg;
        const int kbase     = (ch < 4) ? ch * 64 : cb * 64;

        // Load A tile: 64 rows x 64 cols
        #pragma unroll
        for (int l = 0; l < 4; ++l) {
            int idx = tid + l * 256;          // 0..1023
            int row = idx >> 4;
            int c4  = idx & 15;
            float4 v = make_float4(0.f, 0.f, 0.f, 0.f);
            if (r0 + row < M)
                v = ((const float4*)(srcmat + (size_t)(r0 + row) * DIM + kbase))[c4];
            As[row][c4 * 4 + 0] = v.x;
            As[row][c4 * 4 + 1] = v.y;
            As[row][c4 * 4 + 2] = v.z;
            As[row][c4 * 4 + 3] = v.w;
        }
        // Load B tile: 64 (k) x 64 (c)
        #pragma unroll
        for (int l = 0; l < 4; ++l) {
            int idx = tid + l * 256;
            int row = idx >> 4;
            int c4  = idx & 15;
            float4 v;
            if (ch < 4)
                v = ((const float4*)(loopw + (size_t)(ch * 64 + row) * DIM + cb * 64))[c4];
            else
                v = ((const float4*)(W + (size_t)cb * BD * BD + row * BD))[c4];
            ((float4*)&Bs[row][0])[c4] = v;
        }
        __syncthreads();

        #pragma unroll
        for (int k = 0; k < 64; ++k) {
            float a0 = As[ty * 4 + 0][k];
            float a1 = As[ty * 4 + 1][k];
            float a2 = As[ty * 4 + 2][k];
            float a3 = As[ty * 4 + 3][k];
            float4 b = ((const float4*)&Bs[k][0])[tx];
            acc[0][0] += a0 * b.x; acc[0][1] += a0 * b.y; acc[0][2] += a0 * b.z; acc[0][3] += a0 * b.w;
            acc[1][0] += a1 * b.x; acc[1][1] += a1 * b.y; acc[1][2] += a1 * b.z; acc[1][3] += a1 * b.w;
            acc[2][0] += a2 * b.x; acc[2][1] += a2 * b.y; acc[2][2] += a2 * b.z; acc[2][3] += a2 * b.w;
            acc[3][0] += a3 * b.x; acc[3][1] += a3 * b.y; acc[3][2] += a3 * b.z; acc[3][3] += a3 * b.w;
        }
        __syncthreads();
    }

    // Epilogue: bias + relu, float4 store
    const int c0 = cb * 64 + tx * 4;
    float4 bvec = *(const float4*)(bias + c0);
    #pragma unroll
    for (int i = 0; i < 4; ++i) {
        int r = r0 + ty * 4 + i;
        if (r < M) {
            float4 o;
            o.x = fmaxf(acc[i][0] + bvec.x, 0.f);
            o.y = fmaxf(acc[i][1] + bvec.y, 0.f);
            o.z = fmaxf(acc[i][2] + bvec.z, 0.f);
            o.w = fmaxf(acc[i][3] + bvec.w, 0.f);
            *(float4*)(out + (size_t)r * DIM + c0) = o;
            if (out2)
                *(float4*)(out2 + (size_t)r * DIM + c0) = o;
        }
    }
}

// ---------------------------------------------------------------------------
// Link predictor: for each pair p, e = h[a]*h[b] (elementwise, 256),
//   score = relu(e @ pw1 + pb1) @ pw2 + pb2
// One block (128 threads) per pair; blocks [0,5000) = pos, [5000,10000) = neg.
// ---------------------------------------------------------------------------
__global__ __launch_bounds__(128) void pred_kernel(
    const int*   __restrict__ ps, const int* __restrict__ pd,
    const int*   __restrict__ ns, const int* __restrict__ nd,
    const float* __restrict__ pw1,    // [256, 128]
    const float* __restrict__ pb1,    // [128]
    const float* __restrict__ pw2,    // [128]
    const float* __restrict__ pb2,    // [1]
    float*       __restrict__ out)    // [10000] : pos then neg
{
    const float* h = g_h1;
    __shared__ float e[256];
    __shared__ float ws[4];

    int p = blockIdx.x;
    const int* S;
    const int* D;
    int off;
    if (p < NPAIR) { S = ps; D = pd; off = 0; }
    else           { S = ns; D = nd; off = NPAIR; p -= NPAIR; }

    int a = S[p], b = D[p];
    int tid = threadIdx.x;   // 0..127

    e[tid]       = h[(size_t)a * DIM + tid]       * h[(size_t)b * DIM + tid];
    e[tid + 128] = h[(size_t)a * DIM + 128 + tid] * h[(size_t)b * DIM + 128 + tid];
    __syncthreads();

    float acc = pb1[tid];
    #pragma unroll 8
    for (int j = 0; j < 256; ++j)
        acc += e[j] * pw1[j * 128 + tid];
    acc = fmaxf(acc, 0.f);

    float v = acc * pw2[tid];
    #pragma unroll
    for (int o = 16; o; o >>= 1) v += __shfl_xor_sync(0xFFFFFFFFu, v, o);
    if ((tid & 31) == 0) ws[tid >> 5] = v;
    __syncthreads();
    if (tid == 0)
        out[off + p] = ws[0] + ws[1] + ws[2] + ws[3] + pb2[0];
}

// ---------------------------------------------------------------------------
// Launch
// Inputs (metadata order):
//  0 x [200000,256] f32      1 src0 [800000] i32   2 dst0 [800000] i32
//  3 src1 [160000] i32       4 dst1 [160000] i32
//  5 pos_src 6 pos_dst 7 neg_src 8 neg_dst  (each [5000] i32)
//  9 W0 [4,64,64] 10 loop0 [256,256] 11 b0 [256]
// 12 W1 [4,64,64] 13 loop1 [256,256] 14 b1 [256]
// 15 pw1 [256,128] 16 pb1 [128] 17 pw2 [128,1] 18 pb2 [1]
// Output: h_pos[5000] | h_neg[5000] | h[10000*256]  (f32, flattened in order)
// ---------------------------------------------------------------------------
extern "C" void kernel_launch(void* const* d_in, const int* in_sizes, int n_in,
                              void* d_out, int out_size)
{
    const float* x     = (const float*)d_in[0];
    const int*   src0  = (const int*)d_in[1];
    const int*   dst0  = (const int*)d_in[2];
    const int*   src1  = (const int*)d_in[3];
    const int*   dst1  = (const int*)d_in[4];
    const int*   psrc  = (const int*)d_in[5];
    const int*   pdst  = (const int*)d_in[6];
    const int*   nsrc  = (const int*)d_in[7];
    const int*   ndst  = (const int*)d_in[8];
    const float* W0    = (const float*)d_in[9];
    const float* loop0 = (const float*)d_in[10];
    const float* b0    = (const float*)d_in[11];
    const float* W1    = (const float*)d_in[12];
    const float* loop1 = (const float*)d_in[13];
    const float* b1    = (const float*)d_in[14];
    const float* pw1   = (const float*)d_in[15];
    const float* pb1   = (const float*)d_in[16];
    const float* pw2   = (const float*)d_in[17];
    const float* pb2   = (const float*)d_in[18];
    float*       out   = (float*)d_out;

    // 1. zero aggregation buffers
    zero_kernel<<<1024, 256>>>();

    // 2. layer 0: aggregate raw x, then fused transform (agg0, x -> h0)
    scatter_kernel<0><<<(NE0 + 3) / 4, 256>>>(x, src0, dst0, NE0);
    {
        dim3 grid((N_DST0 + 63) / 64, NBASE);
        layer_kernel<0><<<grid, 256>>>(x, W0, loop0, b0, nullptr, N_DST0);
    }

    // 3. layer 1: aggregate h0, fused transform (agg1, h0 -> h1); mirror h to out
    scatter_kernel<1><<<(NE1 + 3) / 4, 256>>>(nullptr, src1, dst1, NE1);
    {
        dim3 grid((N_DST1 + 63) / 64, NBASE);
        layer_kernel<1><<<grid, 256>>>(nullptr, W1, loop1, b1,
                                       out + 2 * NPAIR, N_DST1);
    }

    // 4. link prediction scores -> out[0:5000] (pos), out[5000:10000] (neg)
    pred_kernel<<<2 * NPAIR, 128>>>(psrc, pdst, nsrc, ndst,
                                    pw1, pb1, pw2, pb2, out);
}

// round 3
// speedup vs baseline: 2.5895x; 2.5895x over previous
#include <cuda_runtime.h>
#include <stdint.h>

// Problem constants
#define N_SRC0 200000
#define N_DST0 50000
#define N_DST1 10000
#define NE0    800000
#define NE1    160000
#define DIM    256
#define NBASE  4
#define BD     64
#define NPAIR  5000

// ---------------------------------------------------------------------------
// Scratch (__device__ globals; kernels reference them directly)
// ---------------------------------------------------------------------------
__device__ float g_agg0[(size_t)N_DST0 * DIM];
__device__ float g_agg1[(size_t)N_DST1 * DIM];
__device__ float g_h0  [(size_t)N_DST0 * DIM];
__device__ float g_h1  [(size_t)N_DST1 * DIM];

__device__ int g_cnt0[N_DST0];
__device__ int g_cnt1[N_DST1];
__device__ int g_rowptr0[N_DST0 + 1];
__device__ int g_rowptr1[N_DST1 + 1];
__device__ int g_cur0[N_DST0];
__device__ int g_cur1[N_DST1];
__device__ int g_esrc0[NE0];
__device__ int g_esrc1[NE1];

// ---------------------------------------------------------------------------
// Zero the per-dst edge counters
// ---------------------------------------------------------------------------
__global__ void zero_cnt_kernel() {
    int stride = gridDim.x * blockDim.x;
    int i0 = blockIdx.x * blockDim.x + threadIdx.x;
    for (int i = i0; i < N_DST0; i += stride) g_cnt0[i] = 0;
    for (int i = i0; i < N_DST1; i += stride) g_cnt1[i] = 0;
}

// ---------------------------------------------------------------------------
// CSR build: count, scan, fill
// ---------------------------------------------------------------------------
template <int WHICH>
__global__ void count_kernel(const int* __restrict__ dst, int ne) {
    int* cnt = WHICH ? g_cnt1 : g_cnt0;
    int e = blockIdx.x * blockDim.x + threadIdx.x;
    if (e < ne) atomicAdd(&cnt[dst[e]], 1);
}

// Single-block exclusive scan (1024 threads, warp-shuffle based).
template <int WHICH>
__global__ __launch_bounds__(1024) void scan_kernel() {
    const int* cnt = WHICH ? g_cnt1 : g_cnt0;
    int* rowptr    = WHICH ? g_rowptr1 : g_rowptr0;
    int* cur       = WHICH ? g_cur1 : g_cur0;
    const int n    = WHICH ? N_DST1 : N_DST0;

    __shared__ int wsum[32];
    __shared__ int carry_s;
    int tid = threadIdx.x, lane = tid & 31, wid = tid >> 5;
    if (tid == 0) carry_s = 0;
    __syncthreads();

    for (int base = 0; base < n; base += 1024) {
        int i = base + tid;
        int v = (i < n) ? cnt[i] : 0;
        // intra-warp inclusive scan
        int incl = v;
        #pragma unroll
        for (int o = 1; o < 32; o <<= 1) {
            int t = __shfl_up_sync(0xFFFFFFFFu, incl, o);
            if (lane >= o) incl += t;
        }
        if (lane == 31) wsum[wid] = incl;
        __syncthreads();
        if (wid == 0) {
            int w = wsum[lane];
            int wi = w;
            #pragma unroll
            for (int o = 1; o < 32; o <<= 1) {
                int t = __shfl_up_sync(0xFFFFFFFFu, wi, o);
                if (lane >= o) wi += t;
            }
            wsum[lane] = wi - w;   // exclusive warp offsets
        }
        __syncthreads();
        int excl = incl - v + wsum[wid] + carry_s;
        if (i < n) { rowptr[i] = excl; cur[i] = excl; }
        __syncthreads();           // everyone read carry_s before update
        if (tid == 1023) carry_s = excl + v;   // absolute running total
        __syncthreads();
    }
    if (tid == 0) rowptr[n] = carry_s;
}

template <int WHICH>
__global__ void fill_kernel(const int* __restrict__ src,
                            const int* __restrict__ dst, int ne) {
    int* cur  = WHICH ? g_cur1 : g_cur0;
    int* esrc = WHICH ? g_esrc1 : g_esrc0;
    int e = blockIdx.x * blockDim.x + threadIdx.x;
    if (e < ne) {
        int p = atomicAdd(&cur[dst[e]], 1);
        esrc[p] = src[e];
    }
}

// ---------------------------------------------------------------------------
// Pull-mode aggregation: agg[d, :] = sum over edges of feat[src, :]
// 128 threads per block = 2 dst rows, 64 threads (float4 each) per row.
// ---------------------------------------------------------------------------
template <int WHICH>
__global__ __launch_bounds__(128) void gather_kernel(const float* __restrict__ featp) {
    const float* feat  = WHICH ? g_h0 : featp;
    float* agg         = WHICH ? g_agg1 : g_agg0;
    const int* rowptr  = WHICH ? g_rowptr1 : g_rowptr0;
    const int* esrc    = WHICH ? g_esrc1 : g_esrc0;
    const int ndst     = WHICH ? N_DST1 : N_DST0;

    int d = blockIdx.x * 2 + (threadIdx.x >> 6);
    int lane = threadIdx.x & 63;
    if (d >= ndst) return;

    int beg = rowptr[d], end = rowptr[d + 1];
    float4 acc = make_float4(0.f, 0.f, 0.f, 0.f);
    const float4* f4 = (const float4*)feat;

    int i = beg;
    for (; i + 1 < end; i += 2) {
        int s0 = esrc[i], s1 = esrc[i + 1];
        float4 v0 = f4[(size_t)s0 * (DIM / 4) + lane];
        float4 v1 = f4[(size_t)s1 * (DIM / 4) + lane];
        acc.x += v0.x + v1.x; acc.y += v0.y + v1.y;
        acc.z += v0.z + v1.z; acc.w += v0.w + v1.w;
    }
    if (i < end) {
        int s0 = esrc[i];
        float4 v0 = f4[(size_t)s0 * (DIM / 4) + lane];
        acc.x += v0.x; acc.y += v0.y; acc.z += v0.z; acc.w += v0.w;
    }
    ((float4*)agg)[(size_t)d * (DIM / 4) + lane] = acc;
}

// ---------------------------------------------------------------------------
// tf32 tensor-core fused layer GEMM.
//   out[r, c] = relu( xd[r,:] @ loopw[:, c]  (K=256)
//                   + agg[r, cb*64:+64] @ W[cb][:, c%64]  (K=64)  + bias[c] )
// Block tile 128x64, 256 threads (8 warps, 4x2 warp grid, 32x32 per warp).
// K = 10 chunks of 32 (8 from xd/loopw, 2 from agg/W).
// ---------------------------------------------------------------------------
__device__ __forceinline__ uint32_t f32_to_tf32(float f) {
    uint32_t u;
    asm("cvt.rna.tf32.f32 %0, %1;" : "=r"(u) : "f"(f));
    return u;
}

template <int LAYER>
__global__ __launch_bounds__(256) void layer_kernel(
    const float* __restrict__ xparam, // layer0: x; layer1 unused
    const float* __restrict__ W,      // [4,64,64]
    const float* __restrict__ loopw,  // [256,256]
    const float* __restrict__ bias,   // [256]
    float*       __restrict__ out2,   // optional mirror (may be null)
    int M)
{
    const float* agg = (LAYER == 0) ? g_agg0 : g_agg1;
    const float* xd  = (LAYER == 0) ? xparam : g_h0;
    float*       out = (LAYER == 0) ? g_h0   : g_h1;

    __shared__ uint32_t As[128][36];   // 128 rows x 32 k (pad 36)
    __shared__ uint32_t Bs[32][72];    // 32 k x 64 n (pad 72 -> conflict-free frags)

    const int cb  = blockIdx.y;        // output column block (0..3)
    const int r0  = blockIdx.x * 128;
    const int tid = threadIdx.x;
    const int lane = tid & 31;
    const int w   = tid >> 5;          // warp 0..7
    const int wm  = w & 3;             // warp row (4)
    const int wn  = w >> 2;            // warp col (2)
    const int t4  = lane >> 2;         // 0..7
    const int tc  = lane & 3;          // 0..3

    float acc[2][4][4];
    #pragma unroll
    for (int mt = 0; mt < 2; ++mt)
        #pragma unroll
        for (int nt = 0; nt < 4; ++nt)
            #pragma unroll
            for (int i = 0; i < 4; ++i) acc[mt][nt][i] = 0.f;

    for (int ch = 0; ch < 10; ++ch) {
        const float* amat = (ch < 8) ? xd : agg;
        const int akbase  = (ch < 8) ? ch * 32 : cb * 64 + (ch - 8) * 32;

        // ---- load A tile: 128x32, 4 float4 per thread ----
        float4 av[4];
        #pragma unroll
        for (int l = 0; l < 4; ++l) {
            int idx = tid + l * 256;        // 0..1023
            int row = idx >> 3;             // /8 (8 float4 per row)
            int c4  = idx & 7;
            av[l] = make_float4(0.f, 0.f, 0.f, 0.f);
            if (r0 + row < M)
                av[l] = *(const float4*)(amat + (size_t)(r0 + row) * DIM + akbase + c4 * 4);
        }
        // ---- load B tile: 32x64, 2 float4 per thread ----
        float4 bv[2];
        #pragma unroll
        for (int l = 0; l < 2; ++l) {
            int idx = tid + l * 256;        // 0..511
            int row = idx >> 4;             // /16 (16 float4 per row)
            int c4  = idx & 15;
            if (ch < 8)
                bv[l] = *(const float4*)(loopw + (size_t)(ch * 32 + row) * DIM + cb * 64 + c4 * 4);
            else
                bv[l] = *(const float4*)(W + (size_t)cb * BD * BD
                                           + (size_t)((ch - 8) * 32 + row) * BD + c4 * 4);
        }

        __syncthreads();   // previous chunk compute done

        #pragma unroll
        for (int l = 0; l < 4; ++l) {
            int idx = tid + l * 256;
            int row = idx >> 3;
            int c4  = idx & 7;
            As[row][c4 * 4 + 0] = f32_to_tf32(av[l].x);
            As[row][c4 * 4 + 1] = f32_to_tf32(av[l].y);
            As[row][c4 * 4 + 2] = f32_to_tf32(av[l].z);
            As[row][c4 * 4 + 3] = f32_to_tf32(av[l].w);
        }
        #pragma unroll
        for (int l = 0; l < 2; ++l) {
            int idx = tid + l * 256;
            int row = idx >> 4;
            int c4  = idx & 15;
            Bs[row][c4 * 4 + 0] = f32_to_tf32(bv[l].x);
            Bs[row][c4 * 4 + 1] = f32_to_tf32(bv[l].y);
            Bs[row][c4 * 4 + 2] = f32_to_tf32(bv[l].z);
            Bs[row][c4 * 4 + 3] = f32_to_tf32(bv[l].w);
        }
        __syncthreads();

        // ---- compute: 4 k-steps of 8 ----
        #pragma unroll
        for (int k0 = 0; k0 < 32; k0 += 8) {
            uint32_t a[2][4];
            #pragma unroll
            for (int mt = 0; mt < 2; ++mt) {
                int mrow = wm * 32 + mt * 16 + t4;
                a[mt][0] = As[mrow][k0 + tc];
                a[mt][1] = As[mrow + 8][k0 + tc];
                a[mt][2] = As[mrow][k0 + tc + 4];
                a[mt][3] = As[mrow + 8][k0 + tc + 4];
            }
            #pragma unroll
            for (int nt = 0; nt < 4; ++nt) {
                int ncol = wn * 32 + nt * 8 + t4;
                uint32_t b0 = Bs[k0 + tc][ncol];
                uint32_t b1 = Bs[k0 + tc + 4][ncol];
                #pragma unroll
                for (int mt = 0; mt < 2; ++mt) {
                    asm volatile(
                        "mma.sync.aligned.m16n8k8.row.col.f32.tf32.tf32.f32 "
                        "{%0,%1,%2,%3}, {%4,%5,%6,%7}, {%8,%9}, {%0,%1,%2,%3};\n"
                        : "+f"(acc[mt][nt][0]), "+f"(acc[mt][nt][1]),
                          "+f"(acc[mt][nt][2]), "+f"(acc[mt][nt][3])
                        : "r"(a[mt][0]), "r"(a[mt][1]), "r"(a[mt][2]), "r"(a[mt][3]),
                          "r"(b0), "r"(b1));
                }
            }
        }
        __syncthreads();
    }

    // ---- epilogue: bias + relu, float2 stores ----
    #pragma unroll
    for (int nt = 0; nt < 4; ++nt) {
        int c = cb * 64 + wn * 32 + nt * 8 + 2 * tc;
        float2 bb = *(const float2*)(bias + c);
        #pragma unroll
        for (int mt = 0; mt < 2; ++mt) {
            int r = r0 + wm * 32 + mt * 16 + t4;
            if (r < M) {
                float2 o;
                o.x = fmaxf(acc[mt][nt][0] + bb.x, 0.f);
                o.y = fmaxf(acc[mt][nt][1] + bb.y, 0.f);
                *(float2*)(out + (size_t)r * DIM + c) = o;
                if (out2) *(float2*)(out2 + (size_t)r * DIM + c) = o;
            }
            if (r + 8 < M) {
                float2 o;
                o.x = fmaxf(acc[mt][nt][2] + bb.x, 0.f);
                o.y = fmaxf(acc[mt][nt][3] + bb.y, 0.f);
                *(float2*)(out + (size_t)(r + 8) * DIM + c) = o;
                if (out2) *(float2*)(out2 + (size_t)(r + 8) * DIM + c) = o;
            }
        }
    }
}

// ---------------------------------------------------------------------------
// Link predictor (unchanged): one 128-thread block per pair.
// ---------------------------------------------------------------------------
__global__ __launch_bounds__(128) void pred_kernel(
    const int*   __restrict__ ps, const int* __restrict__ pd,
    const int*   __restrict__ ns, const int* __restrict__ nd,
    const float* __restrict__ pw1,    // [256, 128]
    const float* __restrict__ pb1,    // [128]
    const float* __restrict__ pw2,    // [128]
    const float* __restrict__ pb2,    // [1]
    float*       __restrict__ out)    // [10000] : pos then neg
{
    const float* h = g_h1;
    __shared__ float e[256];
    __shared__ float ws[4];

    int p = blockIdx.x;
    const int* S;
    const int* D;
    int off;
    if (p < NPAIR) { S = ps; D = pd; off = 0; }
    else           { S = ns; D = nd; off = NPAIR; p -= NPAIR; }

    int a = S[p], b = D[p];
    int tid = threadIdx.x;   // 0..127

    e[tid]       = h[(size_t)a * DIM + tid]       * h[(size_t)b * DIM + tid];
    e[tid + 128] = h[(size_t)a * DIM + 128 + tid] * h[(size_t)b * DIM + 128 + tid];
    __syncthreads();

    float acc = pb1[tid];
    #pragma unroll 8
    for (int j = 0; j < 256; ++j)
        acc += e[j] * pw1[j * 128 + tid];
    acc = fmaxf(acc, 0.f);

    float v = acc * pw2[tid];
    #pragma unroll
    for (int o = 16; o; o >>= 1) v += __shfl_xor_sync(0xFFFFFFFFu, v, o);
    if ((tid & 31) == 0) ws[tid >> 5] = v;
    __syncthreads();
    if (tid == 0)
        out[off + p] = ws[0] + ws[1] + ws[2] + ws[3] + pb2[0];
}

// ---------------------------------------------------------------------------
// Launch
// ---------------------------------------------------------------------------
extern "C" void kernel_launch(void* const* d_in, const int* in_sizes, int n_in,
                              void* d_out, int out_size)
{
    const float* x     = (const float*)d_in[0];
    const int*   src0  = (const int*)d_in[1];
    const int*   dst0  = (const int*)d_in[2];
    const int*   src1  = (const int*)d_in[3];
    const int*   dst1  = (const int*)d_in[4];
    const int*   psrc  = (const int*)d_in[5];
    const int*   pdst  = (const int*)d_in[6];
    const int*   nsrc  = (const int*)d_in[7];
    const int*   ndst  = (const int*)d_in[8];
    const float* W0    = (const float*)d_in[9];
    const float* loop0 = (const float*)d_in[10];
    const float* b0    = (const float*)d_in[11];
    const float* W1    = (const float*)d_in[12];
    const float* loop1 = (const float*)d_in[13];
    const float* b1    = (const float*)d_in[14];
    const float* pw1   = (const float*)d_in[15];
    const float* pb1   = (const float*)d_in[16];
    const float* pw2   = (const float*)d_in[17];
    const float* pb2   = (const float*)d_in[18];
    float*       out   = (float*)d_out;

    // CSR build for both layers (edge lists are data-independent of features)
    zero_cnt_kernel<<<256, 256>>>();
    count_kernel<0><<<(NE0 + 255) / 256, 256>>>(dst0, NE0);
    count_kernel<1><<<(NE1 + 255) / 256, 256>>>(dst1, NE1);
    scan_kernel<0><<<1, 1024>>>();
    scan_kernel<1><<<1, 1024>>>();
    fill_kernel<0><<<(NE0 + 255) / 256, 256>>>(src0, dst0, NE0);
    fill_kernel<1><<<(NE1 + 255) / 256, 256>>>(src1, dst1, NE1);

    // layer 0: pull-aggregate x, fused tf32 transform -> h0
    gather_kernel<0><<<(N_DST0 + 1) / 2, 128>>>(x);
    {
        dim3 grid((N_DST0 + 127) / 128, NBASE);
        layer_kernel<0><<<grid, 256>>>(x, W0, loop0, b0, nullptr, N_DST0);
    }

    // layer 1: pull-aggregate h0, fused transform -> h1 (+mirror to out)
    gather_kernel<1><<<(N_DST1 + 1) / 2, 128>>>(nullptr);
    {
        dim3 grid((N_DST1 + 127) / 128, NBASE);
        layer_kernel<1><<<grid, 256>>>(nullptr, W1, loop1, b1,
                                       out + 2 * NPAIR, N_DST1);
    }

    // link prediction -> out[0:5000] (pos), out[5000:10000] (neg)
    pred_kernel<<<2 * NPAIR, 128>>>(psrc, pdst, nsrc, ndst,
                                    pw1, pb1, pw2, pb2, out);
}